// round 5
// baseline (speedup 1.0000x reference)
#include <cuda_runtime.h>

// Persistent-kernel 2-layer tanh RNN for GB300 (sm_103a).
// One launch, 128 co-resident CTAs, software grid barrier between GEMM stages.
// Inner loops use packed fma.rn.f32x2 (FFMA2) for full-rate fp32.

typedef unsigned long long u64;

namespace {
constexpr int NCTA = 128;   // <= 152 SMs -> single wave, barrier is deadlock-free
constexpr int NTHR = 256;
constexpr int Bm   = 256;   // batch
constexpr int Hd   = 1024;  // hidden
constexpr int Ind  = 256;   // input/output feature dim
constexpr int Tt   = 512;   // sequence length
}

// Scratch state (device globals: allocation-free per harness rules)
__device__ float g_h0[2][Bm * Hd];
__device__ float g_h1[2][Bm * Hd];
__device__ float g_y[Bm * Ind];
__device__ unsigned g_arrive = 0;
__device__ unsigned g_gen = 0;

__device__ __forceinline__ void ffma2(u64 &d, u64 a, u64 b) {
    asm("fma.rn.f32x2 %0, %1, %2, %0;" : "+l"(d) : "l"(a), "l"(b));
}

// Sense-reversal grid barrier. __threadfence() (gpu scope) emits CCTL.IVALL on
// sm_103a, which both releases this CTA's writes and invalidates stale L1 lines
// before the post-barrier reads.
__device__ __forceinline__ void grid_sync() {
    __syncthreads();
    if (threadIdx.x == 0) {
        unsigned gen = *(volatile unsigned *)&g_gen;
        __threadfence();
        if (atomicAdd(&g_arrive, 1u) == NCTA - 1) {
            atomicExch(&g_arrive, 0u);
            __threadfence();
            atomicAdd(&g_gen, 1u);
        } else {
            while (*(volatile unsigned *)&g_gen == gen) { }
            __threadfence();
        }
    }
    __syncthreads();
}

// Accumulate C[m0:m0+TM, n0:n0+TN] += A[M,K](row-major, lda) * Bw[N,K]^T (row-major, ldb)
// over one K segment. 256 threads as a 16x16 grid; thread tile (TM/16) x (TN/16).
// smem A is stored value-DUPLICATED ({a,a} pairs) so the inner loop needs zero MOVs:
// per k-step: RPT + NP LDS.64 + RPT*NP FFMA2.
template <int TM, int TN>
__device__ __forceinline__ void gemm_seg(
    u64 (&acc)[TM / 16][TN / 32],
    const float *__restrict__ A, int lda,
    const float *__restrict__ Bw, int ldb,
    int K, int m0, int n0,
    float *sA, float *sB)
{
    constexpr int RPT = TM / 16;    // output rows per thread
    constexpr int CPT = TN / 16;    // output cols per thread
    constexpr int NP  = TN / 32;    // f32x2 accumulator pairs per row
    constexpr int SA  = 2 * TM + 2; // duplicated-A row stride (pad kills bank conflicts)
    constexpr int SB  = TN + 2;

    const int tid = threadIdx.x;
    const int kk  = tid & 15;   // k lane within chunk
    const int ldr = tid >> 4;   // loader row group
    const int tr  = tid >> 4;   // compute row group
    const int tc  = tid & 15;   // compute col group

    const float *Ab = A + (long)m0 * lda + kk;
    const float *Bb = Bw + (long)n0 * ldb + kk;

    float pa[RPT], pb[CPT];
    const int nch = K >> 4;

    // prefetch chunk 0 into registers
#pragma unroll
    for (int r = 0; r < RPT; ++r) pa[r] = Ab[(ldr + 16 * r) * lda];
#pragma unroll
    for (int c = 0; c < CPT; ++c) pb[c] = Bb[(ldr + 16 * c) * ldb];

    for (int ch = 0; ch < nch; ++ch) {
        __syncthreads();  // previous chunk's compute done; safe to overwrite smem
#pragma unroll
        for (int r = 0; r < RPT; ++r) {
            float v = pa[r];
            *reinterpret_cast<float2 *>(&sA[kk * SA + 2 * (ldr + 16 * r)]) =
                make_float2(v, v);
        }
#pragma unroll
        for (int c = 0; c < CPT; ++c) sB[kk * SB + ldr + 16 * c] = pb[c];

        if (ch + 1 < nch) {  // prefetch next chunk (hides L2 latency under compute)
            int kb = (ch + 1) * 16;
#pragma unroll
            for (int r = 0; r < RPT; ++r) pa[r] = Ab[(ldr + 16 * r) * lda + kb];
#pragma unroll
            for (int c = 0; c < CPT; ++c) pb[c] = Bb[(ldr + 16 * c) * ldb + kb];
        }
        __syncthreads();

#pragma unroll
        for (int k = 0; k < 16; ++k) {
            u64 av[RPT], bv[NP];
#pragma unroll
            for (int r = 0; r < RPT; ++r)
                av[r] = *reinterpret_cast<const u64 *>(
                    &sA[k * SA + 2 * (RPT * tr + r)]);
#pragma unroll
            for (int p = 0; p < NP; ++p)
                bv[p] = *reinterpret_cast<const u64 *>(
                    &sB[k * SB + CPT * tc + 2 * p]);
#pragma unroll
            for (int r = 0; r < RPT; ++r)
#pragma unroll
                for (int p = 0; p < NP; ++p)
                    ffma2(acc[r][p], av[r], bv[p]);
        }
    }
}

__device__ __forceinline__ float2 unpack2(u64 v) {
    union { u64 u; float2 f; } cvt;
    cvt.u = v;
    return cvt.f;
}

__global__ void __launch_bounds__(NTHR, 1) rnn_persistent(
    const float *__restrict__ y0,
    const float *__restrict__ W_ih0, const float *__restrict__ W_hh0,
    const float *__restrict__ b_ih0, const float *__restrict__ b_hh0,
    const float *__restrict__ W_ih1, const float *__restrict__ W_hh1,
    const float *__restrict__ b_ih1, const float *__restrict__ b_hh1,
    const float *__restrict__ fc_W, const float *__restrict__ fc_b,
    float *__restrict__ out)
{
    __shared__ __align__(16) float sA[16 * 66];
    __shared__ __align__(16) float sB[16 * 66];

    const int tid = threadIdx.x;
    const int bid = blockIdx.x;
    const int tr = tid >> 4, tc = tid & 15;

    // ---- phase 0: y <- y0 ; out[:,0,:] <- y0 ; h0,h1 <- 0 (re-done every replay)
    for (int i = bid * NTHR + tid; i < Bm * Ind; i += NCTA * NTHR) {
        float v = y0[i];
        g_y[i] = v;
        out[(i >> 8) * (Tt * Ind) + (i & 255)] = v;
    }
    for (int i = bid * NTHR + tid; i < Bm * Hd; i += NCTA * NTHR) {
        g_h0[0][i] = 0.0f;
        g_h1[0][i] = 0.0f;
    }
    grid_sync();

    for (int s = 1; s < Tt; ++s) {
        const float *h0c = g_h0[(s - 1) & 1];
        float *h0n       = g_h0[s & 1];
        const float *h1c = g_h1[(s - 1) & 1];
        float *h1n       = g_h1[s & 1];

        // ---- stage A: h0n = tanh(y @ W_ih0^T + h0c @ W_hh0^T + b_ih0 + b_hh0)
        {
            const int m0 = (bid >> 4) * 32, n0 = (bid & 15) * 64;  // 8x16 = 128 tiles
            u64 acc[2][2] = {};
            gemm_seg<32, 64>(acc, g_y, Ind, W_ih0, Ind, Ind, m0, n0, sA, sB);
            gemm_seg<32, 64>(acc, h0c, Hd, W_hh0, Hd, Hd, m0, n0, sA, sB);
#pragma unroll
            for (int r = 0; r < 2; ++r)
#pragma unroll
                for (int p = 0; p < 2; ++p) {
                    float2 v = unpack2(acc[r][p]);
                    const int gm = m0 + 2 * tr + r;
                    const int gn = n0 + 4 * tc + 2 * p;
                    v.x = tanhf(v.x + b_ih0[gn] + b_hh0[gn]);
                    v.y = tanhf(v.y + b_ih0[gn + 1] + b_hh0[gn + 1]);
                    *reinterpret_cast<float2 *>(&h0n[gm * Hd + gn]) = v;
                }
        }
        grid_sync();

        // ---- stage B: h1n = tanh(h0n @ W_ih1^T + h1c @ W_hh1^T + b_ih1 + b_hh1)
        {
            const int m0 = (bid >> 4) * 32, n0 = (bid & 15) * 64;
            u64 acc[2][2] = {};
            gemm_seg<32, 64>(acc, h0n, Hd, W_ih1, Hd, Hd, m0, n0, sA, sB);
            gemm_seg<32, 64>(acc, h1c, Hd, W_hh1, Hd, Hd, m0, n0, sA, sB);
#pragma unroll
            for (int r = 0; r < 2; ++r)
#pragma unroll
                for (int p = 0; p < 2; ++p) {
                    float2 v = unpack2(acc[r][p]);
                    const int gm = m0 + 2 * tr + r;
                    const int gn = n0 + 4 * tc + 2 * p;
                    v.x = tanhf(v.x + b_ih1[gn] + b_hh1[gn]);
                    v.y = tanhf(v.y + b_ih1[gn + 1] + b_hh1[gn + 1]);
                    *reinterpret_cast<float2 *>(&h1n[gm * Hd + gn]) = v;
                }
        }
        grid_sync();

        // ---- stage C: y = h1n @ fc_W^T + fc_b ; out[:, s, :] = y
        {
            const int m0 = (bid >> 3) * 16, n0 = (bid & 7) * 32;  // 16x8 = 128 tiles
            u64 acc[1][1] = {};
            gemm_seg<16, 32>(acc, h1n, Hd, fc_W, Hd, Hd, m0, n0, sA, sB);
            float2 v = unpack2(acc[0][0]);
            const int gm = m0 + tr;
            const int gn = n0 + 2 * tc;
            v.x += fc_b[gn];
            v.y += fc_b[gn + 1];
            *reinterpret_cast<float2 *>(&g_y[gm * Ind + gn]) = v;
            *reinterpret_cast<float2 *>(&out[gm * (Tt * Ind) + s * Ind + gn]) = v;
        }
        grid_sync();
    }
}

extern "C" void kernel_launch(void *const *d_in, const int *in_sizes, int n_in,
                              void *d_out, int out_size) {
    (void)in_sizes; (void)n_in; (void)out_size;
    const float *y0    = (const float *)d_in[0];
    // d_in[1] = t (only defines length; unused)
    const float *W_ih0 = (const float *)d_in[2];
    const float *W_hh0 = (const float *)d_in[3];
    const float *b_ih0 = (const float *)d_in[4];
    const float *b_hh0 = (const float *)d_in[5];
    const float *W_ih1 = (const float *)d_in[6];
    const float *W_hh1 = (const float *)d_in[7];
    const float *b_ih1 = (const float *)d_in[8];
    const float *b_hh1 = (const float *)d_in[9];
    const float *fc_W  = (const float *)d_in[10];
    const float *fc_b  = (const float *)d_in[11];
    float *out = (float *)d_out;

    rnn_persistent<<<NCTA, NTHR>>>(y0, W_ih0, W_hh0, b_ih0, b_hh0,
                                   W_ih1, W_hh1, b_ih1, b_hh1,
                                   fc_W, fc_b, out);
}

// round 6
// speedup vs baseline: 1.9845x; 1.9845x over previous
#include <cuda_runtime.h>

// Persistent 2-layer tanh RNN, GB300 (sm_103a).
// Round 5: split-K + 64x64 CTA tiles + 4x4 thread tiles -> 1 B/FLOP shared traffic
// (was 2 B/FLOP; kernel is smem-crossbar-bound per R4 ncu: L1=70.7%, fma=15.2%).
// fp32 exact, packed fma.rn.f32x2 inner loop, deterministic split-K reduction.

typedef unsigned long long u64;

namespace {
constexpr int NCTA = 128;
constexpr int NTHR = 256;
constexpr int Bm   = 256;   // batch
constexpr int Hd   = 1024;  // hidden
constexpr int Ind  = 256;   // input/output dim
constexpr int Tt   = 512;   // seq length
}

// Device-global scratch (allocation-free per harness rules)
__device__ float g_h0[2][Bm * Hd];
__device__ float g_h1[2][Bm * Hd];
__device__ float g_y[Bm * Ind];
__device__ float g_pAB[2][Bm * Hd];   // split-K partials for stages A/B
__device__ float g_pC[8][Bm * Ind];   // split-K partials for stage C
__device__ unsigned g_arrive = 0;
__device__ unsigned g_gen = 0;

__device__ __forceinline__ void ffma2(u64 &d, u64 a, u64 b) {
    asm("fma.rn.f32x2 %0, %1, %2, %0;" : "+l"(d) : "l"(a), "l"(b));
}
__device__ __forceinline__ u64 dup2(float v) {
    u64 r;
    asm("mov.b64 %0, {%1, %1};" : "=l"(r) : "r"(__float_as_uint(v)));
    return r;
}
__device__ __forceinline__ float2 unpack2(u64 v) {
    union { u64 u; float2 f; } c; c.u = v; return c.f;
}

// Sense-reversal grid barrier (validated in R4: rel_err 5e-7).
// __threadfence (gpu scope) -> CCTL.IVALL: releases writes + invalidates stale L1.
__device__ __forceinline__ void grid_sync() {
    __syncthreads();
    if (threadIdx.x == 0) {
        unsigned gen = *(volatile unsigned *)&g_gen;
        __threadfence();
        if (atomicAdd(&g_arrive, 1u) == NCTA - 1) {
            atomicExch(&g_arrive, 0u);
            __threadfence();
            atomicAdd(&g_gen, 1u);
        } else {
            while (*(volatile unsigned *)&g_gen == gen) { }
            __threadfence();
        }
    }
    __syncthreads();
}

// 64x64 tile GEMM segment: acc += A[64,K](lda) * W[64,K]^T(ldb).
// 256 threads as 16x16; thread tile 4 rows x 4 cols (16 outputs).
// Per k per thread: 2 LDS.64 (A row-pairs, natural) + 1 LDS.128 (B scalars)
// + 4 mov.b64 dup (ALU pipe) + 8 FFMA2  => 32 B shared for 32 FLOPs.
__device__ __forceinline__ void gemm64(
    u64 (&acc)[2][4],
    const float *__restrict__ A, int lda,
    const float *__restrict__ Bw, int ldb,
    int K, float *sA, float *sB)
{
    constexpr int SA = 66;  // LDS.64-aligned (264B row), conflict-free A stores
    constexpr int SB = 68;  // LDS.128-aligned (272B row)

    const int tid = threadIdx.x;
    const int kk = tid & 15;    // loader: k lane
    const int mr = tid >> 4;    // loader: row lane
    const int tr = tid >> 4;    // compute: row group (4 rows)
    const int tc = tid & 15;    // compute: col group (4 cols)

    float pa[4], pb[4];
    const int nch = K >> 4;

#pragma unroll
    for (int r = 0; r < 4; ++r) {
        pa[r] = A[(mr + 16 * r) * (long)lda + kk];
        pb[r] = Bw[(mr + 16 * r) * (long)ldb + kk];
    }

    for (int ch = 0; ch < nch; ++ch) {
        __syncthreads();
#pragma unroll
        for (int r = 0; r < 4; ++r) {
            sA[kk * SA + mr + 16 * r] = pa[r];
            sB[kk * SB + mr + 16 * r] = pb[r];
        }
        if (ch + 1 < nch) {
            const int kb = (ch + 1) * 16;
#pragma unroll
            for (int r = 0; r < 4; ++r) {
                pa[r] = A[(mr + 16 * r) * (long)lda + kb + kk];
                pb[r] = Bw[(mr + 16 * r) * (long)ldb + kb + kk];
            }
        }
        __syncthreads();

#pragma unroll
        for (int k = 0; k < 16; ++k) {
            const u64 av0 = *reinterpret_cast<const u64 *>(&sA[k * SA + 4 * tr]);
            const u64 av1 = *reinterpret_cast<const u64 *>(&sA[k * SA + 4 * tr + 2]);
            const float4 bq = *reinterpret_cast<const float4 *>(&sB[k * SB + 4 * tc]);
            const u64 b0 = dup2(bq.x), b1 = dup2(bq.y), b2 = dup2(bq.z), b3 = dup2(bq.w);
            ffma2(acc[0][0], av0, b0); ffma2(acc[0][1], av0, b1);
            ffma2(acc[0][2], av0, b2); ffma2(acc[0][3], av0, b3);
            ffma2(acc[1][0], av1, b0); ffma2(acc[1][1], av1, b1);
            ffma2(acc[1][2], av1, b2); ffma2(acc[1][3], av1, b3);
        }
    }
}

// Store 4x4 thread tile of partials, transposed in-register to float4 rows.
__device__ __forceinline__ void store_partial(
    const u64 (&acc)[2][4], float *__restrict__ dst, int ldc, int m0, int n0)
{
    const int tr = threadIdx.x >> 4, tc = threadIdx.x & 15;
#pragma unroll
    for (int pr = 0; pr < 2; ++pr) {
        const float2 c0 = unpack2(acc[pr][0]), c1 = unpack2(acc[pr][1]);
        const float2 c2 = unpack2(acc[pr][2]), c3 = unpack2(acc[pr][3]);
        const int m = m0 + 4 * tr + 2 * pr;
        *reinterpret_cast<float4 *>(&dst[(long)m * ldc + n0 + 4 * tc]) =
            make_float4(c0.x, c1.x, c2.x, c3.x);
        *reinterpret_cast<float4 *>(&dst[(long)(m + 1) * ldc + n0 + 4 * tc]) =
            make_float4(c0.y, c1.y, c2.y, c3.y);
    }
}

__global__ void __launch_bounds__(NTHR, 1) rnn_persistent(
    const float *__restrict__ y0,
    const float *__restrict__ W_ih0, const float *__restrict__ W_hh0,
    const float *__restrict__ b_ih0, const float *__restrict__ b_hh0,
    const float *__restrict__ W_ih1, const float *__restrict__ W_hh1,
    const float *__restrict__ b_ih1, const float *__restrict__ b_hh1,
    const float *__restrict__ fc_W, const float *__restrict__ fc_b,
    float *__restrict__ out)
{
    __shared__ __align__(16) float sA[16 * 66];
    __shared__ __align__(16) float sB[16 * 68];

    const int tid = threadIdx.x;
    const int bid = blockIdx.x;
    const int gtid = bid * NTHR + tid;

    // Stage A/B mapping: 2 k-splits x (4x16) grid of 64x64 tiles over [256,1024]
    const int ksAB = bid >> 6;
    const int m0AB = ((bid >> 4) & 3) * 64;
    const int n0AB = (bid & 15) * 64;
    // Stage C mapping: 8 k-splits x (4x4) grid of 64x64 tiles over [256,256]
    const int ksC = bid >> 4;
    const int m0C = ((bid >> 2) & 3) * 64;
    const int n0C = (bid & 3) * 64;

    // ---- phase 0 (re-done every graph replay): y<-y0, out[:,0,:]<-y0, h<-0
    for (int i = gtid; i < Bm * Ind; i += NCTA * NTHR) {
        const float v = y0[i];
        g_y[i] = v;
        out[(long)(i >> 8) * (Tt * Ind) + (i & 255)] = v;
    }
    for (int i = gtid; i < Bm * Hd; i += NCTA * NTHR) {
        g_h0[0][i] = 0.0f;
        g_h1[0][i] = 0.0f;
    }
    grid_sync();

    for (int s = 1; s < Tt; ++s) {
        const float *h0c = g_h0[(s - 1) & 1];
        float *h0n       = g_h0[s & 1];
        const float *h1c = g_h1[(s - 1) & 1];
        float *h1n       = g_h1[s & 1];

        // ---- A-gemm: partial[ks] of y@W_ih0^T + h0c@W_hh0^T  (K=1280, split 640/640)
        {
            u64 acc[2][4] = {};
            if (ksAB == 0) {
                gemm64(acc, g_y + (long)m0AB * Ind, Ind,
                       W_ih0 + (long)n0AB * Ind, Ind, 256, sA, sB);
                gemm64(acc, h0c + (long)m0AB * Hd, Hd,
                       W_hh0 + (long)n0AB * Hd, Hd, 384, sA, sB);
            } else {
                gemm64(acc, h0c + (long)m0AB * Hd + 384, Hd,
                       W_hh0 + (long)n0AB * Hd + 384, Hd, 640, sA, sB);
            }
            store_partial(acc, g_pAB[ksAB], Hd, m0AB, n0AB);
        }
        grid_sync();

        // ---- A-reduce: h0n = tanh(p0 + p1 + b_ih0 + b_hh0)
        {
            const int base = gtid * 8;
#pragma unroll
            for (int q = 0; q < 2; ++q) {
                const int i = base + 4 * q;
                const int n = i & (Hd - 1);
                const float4 p0 = *reinterpret_cast<const float4 *>(&g_pAB[0][i]);
                const float4 p1 = *reinterpret_cast<const float4 *>(&g_pAB[1][i]);
                const float4 bi = *reinterpret_cast<const float4 *>(&b_ih0[n]);
                const float4 bh = *reinterpret_cast<const float4 *>(&b_hh0[n]);
                float4 o;
                o.x = tanhf(p0.x + p1.x + bi.x + bh.x);
                o.y = tanhf(p0.y + p1.y + bi.y + bh.y);
                o.z = tanhf(p0.z + p1.z + bi.z + bh.z);
                o.w = tanhf(p0.w + p1.w + bi.w + bh.w);
                *reinterpret_cast<float4 *>(&h0n[i]) = o;
            }
        }
        grid_sync();

        // ---- B-gemm: partial[ks] of h0n@W_ih1^T + h1c@W_hh1^T  (K=2048, split 1024/1024)
        {
            u64 acc[2][4] = {};
            if (ksAB == 0) {
                gemm64(acc, h0n + (long)m0AB * Hd, Hd,
                       W_ih1 + (long)n0AB * Hd, Hd, 1024, sA, sB);
            } else {
                gemm64(acc, h1c + (long)m0AB * Hd, Hd,
                       W_hh1 + (long)n0AB * Hd, Hd, 1024, sA, sB);
            }
            store_partial(acc, g_pAB[ksAB], Hd, m0AB, n0AB);
        }
        grid_sync();

        // ---- B-reduce: h1n = tanh(p0 + p1 + b_ih1 + b_hh1)
        {
            const int base = gtid * 8;
#pragma unroll
            for (int q = 0; q < 2; ++q) {
                const int i = base + 4 * q;
                const int n = i & (Hd - 1);
                const float4 p0 = *reinterpret_cast<const float4 *>(&g_pAB[0][i]);
                const float4 p1 = *reinterpret_cast<const float4 *>(&g_pAB[1][i]);
                const float4 bi = *reinterpret_cast<const float4 *>(&b_ih1[n]);
                const float4 bh = *reinterpret_cast<const float4 *>(&b_hh1[n]);
                float4 o;
                o.x = tanhf(p0.x + p1.x + bi.x + bh.x);
                o.y = tanhf(p0.y + p1.y + bi.y + bh.y);
                o.z = tanhf(p0.z + p1.z + bi.z + bh.z);
                o.w = tanhf(p0.w + p1.w + bi.w + bh.w);
                *reinterpret_cast<float4 *>(&h1n[i]) = o;
            }
        }
        grid_sync();

        // ---- C-gemm: partial[ksC] of h1n@fc_W^T  (K=1024, split 8 x 128)
        {
            u64 acc[2][4] = {};
            gemm64(acc, h1n + (long)m0C * Hd + ksC * 128, Hd,
                   fc_W + (long)n0C * Hd + ksC * 128, Hd, 128, sA, sB);
            store_partial(acc, g_pC[ksC], Ind, m0C, n0C);
        }
        grid_sync();

        // ---- C-reduce: y = sum(partials) + fc_b ; write g_y and out[:, s, :]
        {
            const int i = gtid * 2;
            float2 v = make_float2(0.0f, 0.0f);
#pragma unroll
            for (int p = 0; p < 8; ++p) {
                const float2 pc = *reinterpret_cast<const float2 *>(&g_pC[p][i]);
                v.x += pc.x; v.y += pc.y;
            }
            const int n = i & 255;
            const int m = i >> 8;
            v.x += fc_b[n];
            v.y += fc_b[n + 1];
            *reinterpret_cast<float2 *>(&g_y[i]) = v;
            *reinterpret_cast<float2 *>(&out[(long)m * (Tt * Ind) + s * Ind + n]) = v;
        }
        grid_sync();
    }
}

extern "C" void kernel_launch(void *const *d_in, const int *in_sizes, int n_in,
                              void *d_out, int out_size) {
    (void)in_sizes; (void)n_in; (void)out_size;
    const float *y0    = (const float *)d_in[0];
    // d_in[1] = t (defines length only; unused)
    const float *W_ih0 = (const float *)d_in[2];
    const float *W_hh0 = (const float *)d_in[3];
    const float *b_ih0 = (const float *)d_in[4];
    const float *b_hh0 = (const float *)d_in[5];
    const float *W_ih1 = (const float *)d_in[6];
    const float *W_hh1 = (const float *)d_in[7];
    const float *b_ih1 = (const float *)d_in[8];
    const float *b_hh1 = (const float *)d_in[9];
    const float *fc_W  = (const float *)d_in[10];
    const float *fc_b  = (const float *)d_in[11];
    float *out = (float *)d_out;

    rnn_persistent<<<NCTA, NTHR>>>(y0, W_ih0, W_hh0, b_ih0, b_hh0,
                                   W_ih1, W_hh1, b_ih1, b_hh1,
                                   fc_W, fc_b, out);
}

// round 8
// speedup vs baseline: 4.2848x; 2.1592x over previous
#include <cuda_runtime.h>
#include <cuda_bf16.h>

// Persistent 2-layer tanh RNN, sm_103 baseline tensor cores (mma.sync bf16).
// R7: tcgen05 rejected by harness PTX target (sm_103, no 'a'); use
// mma.sync.m16n8k16 bf16 + ldmatrix instead. bf16x3 split precision:
// a = a_hi + a_lo (bf16); D += ah*bh + ah*bl + al*bh in fp32 accumulators.

typedef unsigned long long u64;
typedef unsigned int u32;

namespace {
constexpr int NCTA = 128;
constexpr int NTHR = 256;
constexpr int Bm = 256, Hd = 1024, Ind = 256, Tt = 512;
// dynamic smem: 4 bf16 tiles (Ah, Al, Wh, Wl), each 128 rows x 64 cols = 16KB
constexpr int SM_AH = 0;
constexpr int SM_AL = 16384;
constexpr int SM_WH = 2 * 16384;
constexpr int SM_WL = 3 * 16384;
constexpr int SMEM_BYTES = 4 * 16384;
}

// ---- device-global state (allocation-free rule) ----
__device__ __align__(16) __nv_bfloat16 g_Wih0h[Hd * Ind], g_Wih0l[Hd * Ind];
__device__ __align__(16) __nv_bfloat16 g_Whh0h[Hd * Hd],  g_Whh0l[Hd * Hd];
__device__ __align__(16) __nv_bfloat16 g_Wih1h[Hd * Hd],  g_Wih1l[Hd * Hd];
__device__ __align__(16) __nv_bfloat16 g_Whh1h[Hd * Hd],  g_Whh1l[Hd * Hd];
__device__ __align__(16) __nv_bfloat16 g_fcWh[Ind * Hd],  g_fcWl[Ind * Hd];
__device__ __align__(16) __nv_bfloat16 g_yh[Bm * Ind],    g_yl[Bm * Ind];
__device__ __align__(16) __nv_bfloat16 g_h0h[2][Bm * Hd], g_h0l[2][Bm * Hd];
__device__ __align__(16) __nv_bfloat16 g_h1h[2][Bm * Hd], g_h1l[2][Bm * Hd];
__device__ float g_pAB[8][Bm * Hd];
__device__ float g_pC[32][Bm * Ind];
__device__ unsigned g_arrive = 0, g_gen = 0;

// ---- helpers ----
__device__ __forceinline__ u32 smem_u32(const void *p) {
    u32 a;
    asm("{ .reg .u64 t; cvta.to.shared.u64 t, %1; cvt.u32.u64 %0, t; }"
        : "=r"(a) : "l"(p));
    return a;
}

#define LDMX4(r, a) \
    asm volatile("ldmatrix.sync.aligned.m8n8.x4.shared.b16 {%0,%1,%2,%3}, [%4];" \
                 : "=r"((r)[0]), "=r"((r)[1]), "=r"((r)[2]), "=r"((r)[3]) : "r"(a))

__device__ __forceinline__ void mma16816(float *c, const u32 *a, u32 b0, u32 b1) {
    asm volatile(
        "mma.sync.aligned.m16n8k16.row.col.f32.bf16.bf16.f32 "
        "{%0,%1,%2,%3}, {%4,%5,%6,%7}, {%8,%9}, {%0,%1,%2,%3};"
        : "+f"(c[0]), "+f"(c[1]), "+f"(c[2]), "+f"(c[3])
        : "r"(a[0]), "r"(a[1]), "r"(a[2]), "r"(a[3]), "r"(b0), "r"(b1));
}

// ---- grid barrier (validated R4/R5) ----
__device__ __forceinline__ void grid_sync() {
    __syncthreads();
    if (threadIdx.x == 0) {
        unsigned gen = *(volatile unsigned *)&g_gen;
        __threadfence();
        if (atomicAdd(&g_arrive, 1u) == NCTA - 1) {
            atomicExch(&g_arrive, 0u);
            __threadfence();
            atomicAdd(&g_gen, 1u);
        } else {
            while (*(volatile unsigned *)&g_gen == gen) { }
            __threadfence();
        }
    }
    __syncthreads();
}

__device__ __forceinline__ void split_bf16(float v, __nv_bfloat16 &h, __nv_bfloat16 &l) {
    h = __float2bfloat16(v);
    l = __float2bfloat16(v - __bfloat162float(h));
}

// Stage one bf16 tile: 128 rows x (B16*8) bf16 cols into SW128-swizzled smem
// (128-byte rows; swizzle closed form: blk' = blk ^ (row&7)).
// B16 = 16-byte blocks per row: 8 for k-chunk 64, 4 for k-chunk 32.
template <int B16>
__device__ __forceinline__ void stage_tile(char *s, const __nv_bfloat16 *g, int ld, int kb) {
    const int tid = threadIdx.x;
#pragma unroll
    for (int j = 0; j < (128 * B16) / NTHR; ++j) {
        const int u = tid + NTHR * j;
        const int row = u / B16, blk = u % B16;
        const uint4 v = *reinterpret_cast<const uint4 *>(&g[(long)row * ld + kb + blk * 8]);
        *reinterpret_cast<uint4 *>(s + row * 128 + ((blk ^ (row & 7)) << 4)) = v;
    }
}

// One K-chunk of a 128x128 CTA tile: stage 4 tiles, then ldmatrix + 3 bf16
// mma passes per k16. Warp (wid) = 2x4 grid; warp tile 64x32 (4 m x 4 n atoms).
__device__ __forceinline__ void gemm_chunk(
    float (&acc)[4][4][4], char *smem, u32 sb,
    const __nv_bfloat16 *Ah, const __nv_bfloat16 *Al, int lda,
    const __nv_bfloat16 *Wh, const __nv_bfloat16 *Wl, int ldw,
    int kb, int kcnt)
{
    if (kcnt == 64) {
        stage_tile<8>(smem + SM_AH, Ah, lda, kb);
        stage_tile<8>(smem + SM_AL, Al, lda, kb);
        stage_tile<8>(smem + SM_WH, Wh, ldw, kb);
        stage_tile<8>(smem + SM_WL, Wl, ldw, kb);
    } else {  // kcnt == 32
        stage_tile<4>(smem + SM_AH, Ah, lda, kb);
        stage_tile<4>(smem + SM_AL, Al, lda, kb);
        stage_tile<4>(smem + SM_WH, Wh, ldw, kb);
        stage_tile<4>(smem + SM_WL, Wl, ldw, kb);
    }
    __syncthreads();

    const int lid = threadIdx.x & 31, wid = threadIdx.x >> 5;
    const int wm = wid >> 2, wn = wid & 3;
    const int nd = kcnt >> 4;

    // per-lane ldmatrix row indices (quad ordering matches mma frag reg order)
    // A (x4): quads = {rows0-7 k0-7, rows8-15 k0-7, rows0-7 k8-15, rows8-15 k8-15}
    const int rA0 = wm * 64 + (lid & 7) + ((lid >> 3) & 1) * 8;  // + ma*16
    const int cAsel = (lid >> 4) & 1;
    // B (x4, two n-atoms): quads = {b0(na0), b1(na0), b0(na1), b1(na1)}
    const int rB0 = wn * 32 + (lid & 7) + ((lid >> 4) & 1) * 8;  // + p*16
    const int cBsel = (lid >> 3) & 1;

    for (int k16 = 0; k16 < nd; ++k16) {
        u32 ah[4][4], al[4][4], bh[2][4], bl[2][4];
#pragma unroll
        for (int ma = 0; ma < 4; ++ma) {
            const int r = rA0 + ma * 16;
            const int cb = k16 * 2 + cAsel;
            const u32 off = (u32)(r * 128 + ((cb ^ (r & 7)) << 4));
            LDMX4(ah[ma], sb + SM_AH + off);
            LDMX4(al[ma], sb + SM_AL + off);
        }
#pragma unroll
        for (int p = 0; p < 2; ++p) {
            const int r = rB0 + p * 16;
            const int cb = k16 * 2 + cBsel;
            const u32 off = (u32)(r * 128 + ((cb ^ (r & 7)) << 4));
            LDMX4(bh[p], sb + SM_WH + off);
            LDMX4(bl[p], sb + SM_WL + off);
        }
        // pass 1: ah * bh, pass 2: ah * bl, pass 3: al * bh
#pragma unroll
        for (int ma = 0; ma < 4; ++ma)
#pragma unroll
            for (int na = 0; na < 4; ++na) {
                const int p = na >> 1, q = (na & 1) * 2;
                mma16816(acc[ma][na], ah[ma], bh[p][q], bh[p][q + 1]);
                mma16816(acc[ma][na], ah[ma], bl[p][q], bl[p][q + 1]);
                mma16816(acc[ma][na], al[ma], bh[p][q], bh[p][q + 1]);
            }
    }
    __syncthreads();  // safe to restage smem next chunk
}

// Dump 128x128 fp32 CTA tile from mma accumulators to a partial buffer.
// c0=(g,2t) c1=(g,2t+1) c2=(g+8,2t) c3=(g+8,2t+1) per atom.
__device__ __forceinline__ void dump_acc(
    const float (&acc)[4][4][4], float *__restrict__ dst, int ldc, int m0, int n0)
{
    const int lid = threadIdx.x & 31, wid = threadIdx.x >> 5;
    const int wm = wid >> 2, wn = wid & 3;
    const int g = lid >> 2, t = lid & 3;
#pragma unroll
    for (int ma = 0; ma < 4; ++ma)
#pragma unroll
        for (int na = 0; na < 4; ++na) {
            const int row = m0 + wm * 64 + ma * 16 + g;
            const int col = n0 + wn * 32 + na * 8 + t * 2;
            *reinterpret_cast<float2 *>(&dst[(long)row * ldc + col]) =
                make_float2(acc[ma][na][0], acc[ma][na][1]);
            *reinterpret_cast<float2 *>(&dst[(long)(row + 8) * ldc + col]) =
                make_float2(acc[ma][na][2], acc[ma][na][3]);
        }
}

// sum 8 split-K partials + biases, tanh, write bf16 hi/lo activations
__device__ __forceinline__ void reduceAB(
    const float *__restrict__ bi, const float *__restrict__ bh,
    __nv_bfloat16 *__restrict__ dh, __nv_bfloat16 *__restrict__ dl, int gtid)
{
    const int base = gtid * 8;
#pragma unroll
    for (int q = 0; q < 2; ++q) {
        const int i = base + 4 * q;
        const int n = i & (Hd - 1);
        float4 a = *reinterpret_cast<const float4 *>(&g_pAB[0][i]);
#pragma unroll
        for (int p = 1; p < 8; ++p) {
            const float4 t = *reinterpret_cast<const float4 *>(&g_pAB[p][i]);
            a.x += t.x; a.y += t.y; a.z += t.z; a.w += t.w;
        }
        const float4 vb = *reinterpret_cast<const float4 *>(&bi[n]);
        const float4 vc = *reinterpret_cast<const float4 *>(&bh[n]);
        const float ox = tanhf(a.x + vb.x + vc.x), oy = tanhf(a.y + vb.y + vc.y);
        const float oz = tanhf(a.z + vb.z + vc.z), ow = tanhf(a.w + vb.w + vc.w);
        __nv_bfloat16 hx, lx, hy, ly, hz, lz, hw, lw;
        split_bf16(ox, hx, lx); split_bf16(oy, hy, ly);
        split_bf16(oz, hz, lz); split_bf16(ow, hw, lw);
        reinterpret_cast<__nv_bfloat162 *>(&dh[i])[0] = __halves2bfloat162(hx, hy);
        reinterpret_cast<__nv_bfloat162 *>(&dh[i])[1] = __halves2bfloat162(hz, hw);
        reinterpret_cast<__nv_bfloat162 *>(&dl[i])[0] = __halves2bfloat162(lx, ly);
        reinterpret_cast<__nv_bfloat162 *>(&dl[i])[1] = __halves2bfloat162(lz, lw);
    }
}

__device__ __forceinline__ void convert_split(
    const float *__restrict__ s, __nv_bfloat16 *dh, __nv_bfloat16 *dl, int n, int gtid)
{
    for (int i = gtid; i < n; i += NCTA * NTHR) split_bf16(s[i], dh[i], dl[i]);
}

__global__ void __launch_bounds__(NTHR, 1) rnn_tc(
    const float *__restrict__ y0,
    const float *__restrict__ W_ih0, const float *__restrict__ W_hh0,
    const float *__restrict__ b_ih0, const float *__restrict__ b_hh0,
    const float *__restrict__ W_ih1, const float *__restrict__ W_hh1,
    const float *__restrict__ b_ih1, const float *__restrict__ b_hh1,
    const float *__restrict__ fc_W, const float *__restrict__ fc_b,
    float *__restrict__ out)
{
    extern __shared__ char smem[];
    const u32 sb = smem_u32(smem);
    const int tid = threadIdx.x, bid = blockIdx.x;
    const int gtid = bid * NTHR + tid;

    // ---- phase 0 (every replay): split weights, init y/out/h
    convert_split(W_ih0, g_Wih0h, g_Wih0l, Hd * Ind, gtid);
    convert_split(W_hh0, g_Whh0h, g_Whh0l, Hd * Hd, gtid);
    convert_split(W_ih1, g_Wih1h, g_Wih1l, Hd * Hd, gtid);
    convert_split(W_hh1, g_Whh1h, g_Whh1l, Hd * Hd, gtid);
    convert_split(fc_W, g_fcWh, g_fcWl, Ind * Hd, gtid);
    for (int i = gtid; i < Bm * Ind; i += NCTA * NTHR) {
        const float v = y0[i];
        split_bf16(v, g_yh[i], g_yl[i]);
        out[(long)(i >> 8) * (Tt * Ind) + (i & 255)] = v;
    }
    for (int i = gtid; i < Bm * Hd; i += NCTA * NTHR) {
        g_h0h[0][i] = __float2bfloat16(0.0f); g_h0l[0][i] = __float2bfloat16(0.0f);
        g_h1h[0][i] = __float2bfloat16(0.0f); g_h1l[0][i] = __float2bfloat16(0.0f);
    }
    grid_sync();

    // tile mappings: A/B: 8 k-splits x (2m x 8n); C: 32 k-splits x (2m x 2n)
    const int ksAB = bid >> 4, m0AB = ((bid >> 3) & 1) * 128, n0AB = (bid & 7) * 128;
    const int ksC = bid >> 2, m0C = ((bid >> 1) & 1) * 128, n0C = (bid & 1) * 128;

    for (int s = 1; s < Tt; ++s) {
        const int cb = (s - 1) & 1, nb = s & 1;

        // ---- stage A: y@W_ih0^T (K=256) + h0c@W_hh0^T (K=1024), 8-way split-K
        {
            float acc[4][4][4] = {};
            gemm_chunk(acc, smem, sb,
                       g_yh + (long)m0AB * Ind, g_yl + (long)m0AB * Ind, Ind,
                       g_Wih0h + (long)n0AB * Ind, g_Wih0l + (long)n0AB * Ind, Ind,
                       ksAB * 32, 32);
            gemm_chunk(acc, smem, sb,
                       g_h0h[cb] + (long)m0AB * Hd, g_h0l[cb] + (long)m0AB * Hd, Hd,
                       g_Whh0h + (long)n0AB * Hd, g_Whh0l + (long)n0AB * Hd, Hd,
                       ksAB * 128, 64);
            gemm_chunk(acc, smem, sb,
                       g_h0h[cb] + (long)m0AB * Hd, g_h0l[cb] + (long)m0AB * Hd, Hd,
                       g_Whh0h + (long)n0AB * Hd, g_Whh0l + (long)n0AB * Hd, Hd,
                       ksAB * 128 + 64, 64);
            dump_acc(acc, g_pAB[ksAB], Hd, m0AB, n0AB);
        }
        grid_sync();
        reduceAB(b_ih0, b_hh0, g_h0h[nb], g_h0l[nb], gtid);
        grid_sync();

        // ---- stage B: h0n@W_ih1^T (K=1024) + h1c@W_hh1^T (K=1024), 8-way split-K
        {
            float acc[4][4][4] = {};
            gemm_chunk(acc, smem, sb,
                       g_h0h[nb] + (long)m0AB * Hd, g_h0l[nb] + (long)m0AB * Hd, Hd,
                       g_Wih1h + (long)n0AB * Hd, g_Wih1l + (long)n0AB * Hd, Hd,
                       ksAB * 128, 64);
            gemm_chunk(acc, smem, sb,
                       g_h0h[nb] + (long)m0AB * Hd, g_h0l[nb] + (long)m0AB * Hd, Hd,
                       g_Wih1h + (long)n0AB * Hd, g_Wih1l + (long)n0AB * Hd, Hd,
                       ksAB * 128 + 64, 64);
            gemm_chunk(acc, smem, sb,
                       g_h1h[cb] + (long)m0AB * Hd, g_h1l[cb] + (long)m0AB * Hd, Hd,
                       g_Whh1h + (long)n0AB * Hd, g_Whh1l + (long)n0AB * Hd, Hd,
                       ksAB * 128, 64);
            gemm_chunk(acc, smem, sb,
                       g_h1h[cb] + (long)m0AB * Hd, g_h1l[cb] + (long)m0AB * Hd, Hd,
                       g_Whh1h + (long)n0AB * Hd, g_Whh1l + (long)n0AB * Hd, Hd,
                       ksAB * 128 + 64, 64);
            dump_acc(acc, g_pAB[ksAB], Hd, m0AB, n0AB);
        }
        grid_sync();
        reduceAB(b_ih1, b_hh1, g_h1h[nb], g_h1l[nb], gtid);
        grid_sync();

        // ---- stage C: h1n@fc_W^T (K=1024), 32-way split-K (K=32 each)
        {
            float acc[4][4][4] = {};
            gemm_chunk(acc, smem, sb,
                       g_h1h[nb] + (long)m0C * Hd, g_h1l[nb] + (long)m0C * Hd, Hd,
                       g_fcWh + (long)n0C * Hd, g_fcWl + (long)n0C * Hd, Hd,
                       ksC * 32, 32);
            dump_acc(acc, g_pC[ksC], Ind, m0C, n0C);
        }
        grid_sync();

        // ---- C-reduce: y = sum(32 partials) + fc_b -> out + bf16 hi/lo feedback
        {
            const int i = gtid * 2;
            float2 v = make_float2(0.0f, 0.0f);
#pragma unroll
            for (int p = 0; p < 32; ++p) {
                const float2 t = *reinterpret_cast<const float2 *>(&g_pC[p][i]);
                v.x += t.x; v.y += t.y;
            }
            const int n = i & 255, m = i >> 8;
            v.x += fc_b[n];
            v.y += fc_b[n + 1];
            *reinterpret_cast<float2 *>(&out[(long)m * (Tt * Ind) + s * Ind + n]) = v;
            __nv_bfloat16 hx, lx, hy, ly;
            split_bf16(v.x, hx, lx);
            split_bf16(v.y, hy, ly);
            *reinterpret_cast<__nv_bfloat162 *>(&g_yh[i]) = __halves2bfloat162(hx, hy);
            *reinterpret_cast<__nv_bfloat162 *>(&g_yl[i]) = __halves2bfloat162(lx, ly);
        }
        grid_sync();
    }
}

extern "C" void kernel_launch(void *const *d_in, const int *in_sizes, int n_in,
                              void *d_out, int out_size) {
    (void)in_sizes; (void)n_in; (void)out_size;
    const float *y0    = (const float *)d_in[0];
    // d_in[1] = t (length only; unused)
    const float *W_ih0 = (const float *)d_in[2];
    const float *W_hh0 = (const float *)d_in[3];
    const float *b_ih0 = (const float *)d_in[4];
    const float *b_hh0 = (const float *)d_in[5];
    const float *W_ih1 = (const float *)d_in[6];
    const float *W_hh1 = (const float *)d_in[7];
    const float *b_ih1 = (const float *)d_in[8];
    const float *b_hh1 = (const float *)d_in[9];
    const float *fc_W  = (const float *)d_in[10];
    const float *fc_b  = (const float *)d_in[11];
    float *out = (float *)d_out;

    cudaFuncSetAttribute(rnn_tc, cudaFuncAttributeMaxDynamicSharedMemorySize, SMEM_BYTES);
    rnn_tc<<<NCTA, NTHR, SMEM_BYTES>>>(y0, W_ih0, W_hh0, b_ih0, b_hh0,
                                       W_ih1, W_hh1, b_ih1, b_hh1,
                                       fc_W, fc_b, out);
}

// round 9
// speedup vs baseline: 5.2761x; 1.2314x over previous
#include <cuda_runtime.h>
#include <cuda_bf16.h>

// Persistent 2-layer tanh RNN, sm_103 baseline tensor cores (mma.sync bf16 x3).
// R8: (1) cp.async double-buffered staging (latency was exposed: issue 7.9%),
//     (2) fc layer folded into stage A via precomputed M0 = W_ih0 @ fc_W
//         (4 grid barriers/step instead of 6, stage C off the critical path),
//     (3) all outputs batched into one parallel GEMM over stored h1 history.

typedef unsigned long long u64;
typedef unsigned int u32;

namespace {
constexpr int NCTA = 128;
constexpr int NTHR = 256;
constexpr int Bm = 256, Hd = 1024, Ind = 256, Tt = 512;
// double-buffered dynamic smem: per buffer 4 bf16 tiles (Ah, Al, Wh, Wl) x 16KB
constexpr int BUFB = 65536;
constexpr int T_AH = 0, T_AL = 16384, T_WH = 32768, T_WL = 49152;
constexpr int SMEM_BYTES = 2 * BUFB;  // 128KB
}

// ---- device-global state (allocation-free rule) ----
__device__ __align__(16) __nv_bfloat16 g_Wih0h[Hd * Ind], g_Wih0l[Hd * Ind];
__device__ __align__(16) __nv_bfloat16 g_Whh0h[Hd * Hd],  g_Whh0l[Hd * Hd];
__device__ __align__(16) __nv_bfloat16 g_Wih1h[Hd * Hd],  g_Wih1l[Hd * Hd];
__device__ __align__(16) __nv_bfloat16 g_Whh1h[Hd * Hd],  g_Whh1l[Hd * Hd];
__device__ __align__(16) __nv_bfloat16 g_M0h[Hd * Hd],    g_M0l[Hd * Hd];
__device__ __align__(16) __nv_bfloat16 g_fcWh[Ind * Hd],  g_fcWl[Ind * Hd];
__device__ __align__(16) __nv_bfloat16 g_fcWTh[Hd * Ind], g_fcWTl[Hd * Ind];
__device__ __align__(16) __nv_bfloat16 g_yh[Bm * Ind],    g_yl[Bm * Ind];
__device__ __align__(16) __nv_bfloat16 g_h0h[2][Bm * Hd], g_h0l[2][Bm * Hd];
// full h1 history (hi/lo) for the batched output GEMM: 512 x 256 x 1024
__device__ __align__(16) __nv_bfloat16 g_H1h[Tt * Bm * Hd];
__device__ __align__(16) __nv_bfloat16 g_H1l[Tt * Bm * Hd];
__device__ float g_biasA1[Hd], g_biasAf[Hd], g_biasB[Hd];
__device__ float g_pAB[8][Bm * Hd];   // split-K partials (also M0 scratch: 2 x 1M)
__device__ unsigned g_arrive = 0, g_gen = 0;

// ---- helpers ----
__device__ __forceinline__ u32 smem_u32(const void *p) {
    u32 a;
    asm("{ .reg .u64 t; cvta.to.shared.u64 t, %1; cvt.u32.u64 %0, t; }"
        : "=r"(a) : "l"(p));
    return a;
}

#define LDMX4(r, a) \
    asm volatile("ldmatrix.sync.aligned.m8n8.x4.shared.b16 {%0,%1,%2,%3}, [%4];" \
                 : "=r"((r)[0]), "=r"((r)[1]), "=r"((r)[2]), "=r"((r)[3]) : "r"(a))

__device__ __forceinline__ void mma16816(float *c, const u32 *a, u32 b0, u32 b1) {
    asm volatile(
        "mma.sync.aligned.m16n8k16.row.col.f32.bf16.bf16.f32 "
        "{%0,%1,%2,%3}, {%4,%5,%6,%7}, {%8,%9}, {%0,%1,%2,%3};"
        : "+f"(c[0]), "+f"(c[1]), "+f"(c[2]), "+f"(c[3])
        : "r"(a[0]), "r"(a[1]), "r"(a[2]), "r"(a[3]), "r"(b0), "r"(b1));
}

// ---- grid barrier (validated R4-R7) ----
__device__ __forceinline__ void grid_sync() {
    __syncthreads();
    if (threadIdx.x == 0) {
        unsigned gen = *(volatile unsigned *)&g_gen;
        __threadfence();
        if (atomicAdd(&g_arrive, 1u) == NCTA - 1) {
            atomicExch(&g_arrive, 0u);
            __threadfence();
            atomicAdd(&g_gen, 1u);
        } else {
            while (*(volatile unsigned *)&g_gen == gen) { }
            __threadfence();
        }
    }
    __syncthreads();
}

__device__ __forceinline__ void split_bf16(float v, __nv_bfloat16 &h, __nv_bfloat16 &l) {
    h = __float2bfloat16(v);
    l = __float2bfloat16(v - __bfloat162float(h));
}

// cp.async one 128x64 bf16 tile (SW128 xor swizzle) into smem. 16 B per copy.
__device__ __forceinline__ void stage_async(u32 sdst, const __nv_bfloat16 *g,
                                            int ld, int kb) {
    const int tid = threadIdx.x;
#pragma unroll
    for (int j = 0; j < 4; ++j) {
        const int u = tid + NTHR * j;
        const int row = u >> 3, blk = u & 7;
        const size_t src = __cvta_generic_to_global(&g[(long)row * ld + kb + blk * 8]);
        const u32 dst = sdst + row * 128 + ((blk ^ (row & 7)) << 4);
        asm volatile("cp.async.cg.shared.global [%0], [%1], 16;"
                     :: "r"(dst), "l"(src) : "memory");
    }
}

__device__ __forceinline__ void issue_chunk(
    u32 sbuf, const __nv_bfloat16 *Ah, const __nv_bfloat16 *Al, int lda,
    const __nv_bfloat16 *Wh, const __nv_bfloat16 *Wl, int ldw, int kb) {
    stage_async(sbuf + T_AH, Ah, lda, kb);
    stage_async(sbuf + T_AL, Al, lda, kb);
    stage_async(sbuf + T_WH, Wh, ldw, kb);
    stage_async(sbuf + T_WL, Wl, ldw, kb);
    asm volatile("cp.async.commit_group;" ::: "memory");
}

// MMA over one staged 64-k chunk. 8 warps as 2x4; warp tile 64x32.
// 3 precision passes: ah*bh + ah*bl + al*bh.
__device__ __forceinline__ void mma_tile(float (&acc)[4][4][4], u32 sbase) {
    const int lid = threadIdx.x & 31, wid = threadIdx.x >> 5;
    const int wm = wid >> 2, wn = wid & 3;
    const int rA0 = wm * 64 + (lid & 7) + ((lid >> 3) & 1) * 8;
    const int cAsel = (lid >> 4) & 1;
    const int rB0 = wn * 32 + (lid & 7) + ((lid >> 4) & 1) * 8;
    const int cBsel = (lid >> 3) & 1;
#pragma unroll
    for (int k16 = 0; k16 < 4; ++k16) {
        u32 ah[4][4], al[4][4], bh[2][4], bl[2][4];
#pragma unroll
        for (int ma = 0; ma < 4; ++ma) {
            const int r = rA0 + ma * 16;
            const u32 off = (u32)(r * 128 + (((k16 * 2 + cAsel) ^ (r & 7)) << 4));
            LDMX4(ah[ma], sbase + T_AH + off);
            LDMX4(al[ma], sbase + T_AL + off);
        }
#pragma unroll
        for (int p = 0; p < 2; ++p) {
            const int r = rB0 + p * 16;
            const u32 off = (u32)(r * 128 + (((k16 * 2 + cBsel) ^ (r & 7)) << 4));
            LDMX4(bh[p], sbase + T_WH + off);
            LDMX4(bl[p], sbase + T_WL + off);
        }
#pragma unroll
        for (int ma = 0; ma < 4; ++ma)
#pragma unroll
            for (int na = 0; na < 4; ++na) {
                const int p = na >> 1, q = (na & 1) * 2;
                mma16816(acc[ma][na], ah[ma], bh[p][q], bh[p][q + 1]);
                mma16816(acc[ma][na], ah[ma], bl[p][q], bl[p][q + 1]);
                mma16816(acc[ma][na], al[ma], bh[p][q], bh[p][q + 1]);
            }
    }
}

// Double-buffered pipelined GEMM over nch 64-k chunks starting at kb.
__device__ __forceinline__ void gemm_pipe(
    float (&acc)[4][4][4], u32 sb,
    const __nv_bfloat16 *Ah, const __nv_bfloat16 *Al, int lda,
    const __nv_bfloat16 *Wh, const __nv_bfloat16 *Wl, int ldw,
    int kb, int nch)
{
    issue_chunk(sb, Ah, Al, lda, Wh, Wl, ldw, kb);
    if (nch > 1) issue_chunk(sb + BUFB, Ah, Al, lda, Wh, Wl, ldw, kb + 64);
    for (int i = 0; i < nch; ++i) {
        if (i + 1 < nch)
            asm volatile("cp.async.wait_group 1;" ::: "memory");
        else
            asm volatile("cp.async.wait_group 0;" ::: "memory");
        __syncthreads();
        mma_tile(acc, sb + (u32)((i & 1) * BUFB));
        __syncthreads();
        if (i + 2 < nch)
            issue_chunk(sb + (u32)((i & 1) * BUFB), Ah, Al, lda, Wh, Wl, ldw,
                        kb + 64 * (i + 2));
    }
}

// Dump 128x128 fp32 accumulator tile to a partial buffer.
__device__ __forceinline__ void dump_acc(
    const float (&acc)[4][4][4], float *__restrict__ dst, int ldc, int m0, int n0)
{
    const int lid = threadIdx.x & 31, wid = threadIdx.x >> 5;
    const int wm = wid >> 2, wn = wid & 3;
    const int g = lid >> 2, t = lid & 3;
#pragma unroll
    for (int ma = 0; ma < 4; ++ma)
#pragma unroll
        for (int na = 0; na < 4; ++na) {
            const int row = m0 + wm * 64 + ma * 16 + g;
            const int col = n0 + wn * 32 + na * 8 + t * 2;
            *reinterpret_cast<float2 *>(&dst[(long)row * ldc + col]) =
                make_float2(acc[ma][na][0], acc[ma][na][1]);
            *reinterpret_cast<float2 *>(&dst[(long)(row + 8) * ldc + col]) =
                make_float2(acc[ma][na][2], acc[ma][na][3]);
        }
}

// sum 8 split-K partials + bias, tanh, write bf16 hi/lo activations
__device__ __forceinline__ void reduce_stage(
    const float *__restrict__ bias,
    __nv_bfloat16 *__restrict__ dh, __nv_bfloat16 *__restrict__ dl, int gtid)
{
    const int base = gtid * 8;
#pragma unroll
    for (int q = 0; q < 2; ++q) {
        const int i = base + 4 * q;
        const int n = i & (Hd - 1);
        float4 a = *reinterpret_cast<const float4 *>(&g_pAB[0][i]);
#pragma unroll
        for (int p = 1; p < 8; ++p) {
            const float4 t = *reinterpret_cast<const float4 *>(&g_pAB[p][i]);
            a.x += t.x; a.y += t.y; a.z += t.z; a.w += t.w;
        }
        const float4 vb = *reinterpret_cast<const float4 *>(&bias[n]);
        const float ox = tanhf(a.x + vb.x), oy = tanhf(a.y + vb.y);
        const float oz = tanhf(a.z + vb.z), ow = tanhf(a.w + vb.w);
        __nv_bfloat16 hx, lx, hy, ly, hz, lz, hw, lw;
        split_bf16(ox, hx, lx); split_bf16(oy, hy, ly);
        split_bf16(oz, hz, lz); split_bf16(ow, hw, lw);
        reinterpret_cast<__nv_bfloat162 *>(&dh[i])[0] = __halves2bfloat162(hx, hy);
        reinterpret_cast<__nv_bfloat162 *>(&dh[i])[1] = __halves2bfloat162(hz, hw);
        reinterpret_cast<__nv_bfloat162 *>(&dl[i])[0] = __halves2bfloat162(lx, ly);
        reinterpret_cast<__nv_bfloat162 *>(&dl[i])[1] = __halves2bfloat162(lz, lw);
    }
}

__device__ __forceinline__ void convert_split(
    const float *__restrict__ s, __nv_bfloat16 *dh, __nv_bfloat16 *dl, int n, int gtid)
{
    for (int i = gtid; i < n; i += NCTA * NTHR) split_bf16(s[i], dh[i], dl[i]);
}

// Final-GEMM epilogue: out[:, s, :] tile = acc + fc_b
__device__ __forceinline__ void final_store(
    const float (&acc)[4][4][4], float *__restrict__ out,
    const float *__restrict__ fc_b, int s, int m0, int n0)
{
    const int lid = threadIdx.x & 31, wid = threadIdx.x >> 5;
    const int wm = wid >> 2, wn = wid & 3;
    const int g = lid >> 2, t = lid & 3;
#pragma unroll
    for (int ma = 0; ma < 4; ++ma)
#pragma unroll
        for (int na = 0; na < 4; ++na) {
            const int row = m0 + wm * 64 + ma * 16 + g;
            const int col = n0 + wn * 32 + na * 8 + t * 2;
            const float bx = fc_b[col], by = fc_b[col + 1];
            *reinterpret_cast<float2 *>(
                &out[(long)row * (Tt * Ind) + (long)s * Ind + col]) =
                make_float2(acc[ma][na][0] + bx, acc[ma][na][1] + by);
            *reinterpret_cast<float2 *>(
                &out[(long)(row + 8) * (Tt * Ind) + (long)s * Ind + col]) =
                make_float2(acc[ma][na][2] + bx, acc[ma][na][3] + by);
        }
}

__global__ void __launch_bounds__(NTHR, 1) rnn_tc(
    const float *__restrict__ y0,
    const float *__restrict__ W_ih0, const float *__restrict__ W_hh0,
    const float *__restrict__ b_ih0, const float *__restrict__ b_hh0,
    const float *__restrict__ W_ih1, const float *__restrict__ W_hh1,
    const float *__restrict__ b_ih1, const float *__restrict__ b_hh1,
    const float *__restrict__ fc_W, const float *__restrict__ fc_b,
    float *__restrict__ out)
{
    extern __shared__ char smem[];
    const u32 sb = smem_u32(smem);
    const int tid = threadIdx.x, bid = blockIdx.x;
    const int gtid = bid * NTHR + tid;
    const int stride = NCTA * NTHR;

    // ---- phase 0a (every replay): splits, transpose, init, biases
    convert_split(W_ih0, g_Wih0h, g_Wih0l, Hd * Ind, gtid);
    convert_split(W_hh0, g_Whh0h, g_Whh0l, Hd * Hd, gtid);
    convert_split(W_ih1, g_Wih1h, g_Wih1l, Hd * Hd, gtid);
    convert_split(W_hh1, g_Whh1h, g_Whh1l, Hd * Hd, gtid);
    convert_split(fc_W, g_fcWh, g_fcWl, Ind * Hd, gtid);
    for (int i = gtid; i < Hd * Ind; i += stride) {  // fcWT[j][k] = fc_W[k][j]
        const int j = i >> 8, k = i & 255;
        split_bf16(fc_W[(long)k * Hd + j], g_fcWTh[i], g_fcWTl[i]);
    }
    for (int i = gtid; i < Bm * Ind; i += stride) {
        const float v = y0[i];
        split_bf16(v, g_yh[i], g_yl[i]);
        out[(long)(i >> 8) * (Tt * Ind) + (i & 255)] = v;  // out[:, 0, :]
    }
    for (int i = gtid; i < Bm * Hd; i += stride) {
        const __nv_bfloat16 z = __float2bfloat16(0.0f);
        g_h0h[0][i] = z; g_h0l[0][i] = z;
        g_H1h[i] = z;    g_H1l[i] = z;   // history slot 0 = h1 initial state
    }
    for (int j = gtid; j < Hd; j += stride) {
        const float s1 = b_ih0[j] + b_hh0[j];
        g_biasA1[j] = s1;
        float a = 0.0f;
        const float *wr = &W_ih0[(long)j * Ind];
        for (int k = 0; k < Ind; ++k) a += wr[k] * fc_b[k];
        g_biasAf[j] = a + s1;              // (fc_b @ W_ih0^T + b_ih0 + b_hh0)
        g_biasB[j] = b_ih1[j] + b_hh1[j];
    }
    grid_sync();

    // ---- phase 0b: M0 = W_ih0 @ fc_W  (1024x1024, K=256), 64 tiles x 2 k-splits
    {
        const int ks = bid >> 6, tj = bid & 63, tm = tj >> 3, tn = tj & 7;
        float acc[4][4][4] = {};
        gemm_pipe(acc, sb,
                  g_Wih0h + (long)tm * 128 * Ind, g_Wih0l + (long)tm * 128 * Ind, Ind,
                  g_fcWTh + (long)tn * 128 * Ind, g_fcWTl + (long)tn * 128 * Ind, Ind,
                  ks * 128, 2);
        dump_acc(acc, &g_pAB[0][0] + (long)ks * (Hd * Hd / 2) * 2, Hd, tm * 128, tn * 128);
    }
    grid_sync();
    {   // M0 reduce + split to bf16 hi/lo
        const float *p0 = &g_pAB[0][0];
        const float *p1 = p0 + (long)Hd * Hd;
        for (int i = gtid * 4; i < Hd * Hd; i += stride * 4) {
            const float4 a = *reinterpret_cast<const float4 *>(&p0[i]);
            const float4 b = *reinterpret_cast<const float4 *>(&p1[i]);
            split_bf16(a.x + b.x, g_M0h[i], g_M0l[i]);
            split_bf16(a.y + b.y, g_M0h[i + 1], g_M0l[i + 1]);
            split_bf16(a.z + b.z, g_M0h[i + 2], g_M0l[i + 2]);
            split_bf16(a.w + b.w, g_M0h[i + 3], g_M0l[i + 3]);
        }
    }
    grid_sync();

    // tile mapping: 8 k-splits x (2m x 8n) over [256, 1024]
    const int ksAB = bid >> 4, m0AB = ((bid >> 3) & 1) * 128, n0AB = (bid & 7) * 128;

    for (int s = 1; s < Tt; ++s) {
        const int cb = (s - 1) & 1, nb = s & 1;
        const __nv_bfloat16 *h1ph = g_H1h + (long)(s - 1) * Bm * Hd;
        const __nv_bfloat16 *h1pl = g_H1l + (long)(s - 1) * Bm * Hd;

        // ---- stage A: [h1prev | h0c] @ [M0 | W_hh0]^T  (K=2048; s==1: y0 @ W_ih0^T)
        {
            float acc[4][4][4] = {};
            if (ksAB < 4) {
                if (s == 1)
                    gemm_pipe(acc, sb,
                              g_yh + (long)m0AB * Ind, g_yl + (long)m0AB * Ind, Ind,
                              g_Wih0h + (long)n0AB * Ind, g_Wih0l + (long)n0AB * Ind, Ind,
                              ksAB * 64, 1);
                else
                    gemm_pipe(acc, sb,
                              h1ph + (long)m0AB * Hd, h1pl + (long)m0AB * Hd, Hd,
                              g_M0h + (long)n0AB * Hd, g_M0l + (long)n0AB * Hd, Hd,
                              ksAB * 256, 4);
            } else {
                gemm_pipe(acc, sb,
                          g_h0h[cb] + (long)m0AB * Hd, g_h0l[cb] + (long)m0AB * Hd, Hd,
                          g_Whh0h + (long)n0AB * Hd, g_Whh0l + (long)n0AB * Hd, Hd,
                          (ksAB - 4) * 256, 4);
            }
            dump_acc(acc, g_pAB[ksAB], Hd, m0AB, n0AB);
        }
        grid_sync();
        reduce_stage(s == 1 ? g_biasA1 : g_biasAf, g_h0h[nb], g_h0l[nb], gtid);
        grid_sync();

        // ---- stage B: [h0n | h1prev] @ [W_ih1 | W_hh1]^T  (K=2048)
        {
            float acc[4][4][4] = {};
            if (ksAB < 4)
                gemm_pipe(acc, sb,
                          g_h0h[nb] + (long)m0AB * Hd, g_h0l[nb] + (long)m0AB * Hd, Hd,
                          g_Wih1h + (long)n0AB * Hd, g_Wih1l + (long)n0AB * Hd, Hd,
                          ksAB * 256, 4);
            else
                gemm_pipe(acc, sb,
                          h1ph + (long)m0AB * Hd, h1pl + (long)m0AB * Hd, Hd,
                          g_Whh1h + (long)n0AB * Hd, g_Whh1l + (long)n0AB * Hd, Hd,
                          (ksAB - 4) * 256, 4);
            dump_acc(acc, g_pAB[ksAB], Hd, m0AB, n0AB);
        }
        grid_sync();
        reduce_stage(g_biasB, g_H1h + (long)s * Bm * Hd, g_H1l + (long)s * Bm * Hd, gtid);
        grid_sync();
    }

    // ---- batched output GEMM: out[:, s, :] = H1[s] @ fc_W^T + fc_b, s = 1..511
    // jobs: 511 steps x 2 m-tiles x 2 n-tiles = 2044; K=1024 full per job
    for (int job = bid; job < (Tt - 1) * 4; job += NCTA) {
        const int ntile = job & 1;
        const int rt = job >> 1;
        const int s = 1 + (rt >> 1);
        const int m0 = (rt & 1) * 128, n0 = ntile * 128;
        float acc[4][4][4] = {};
        gemm_pipe(acc, sb,
                  g_H1h + (long)s * Bm * Hd + (long)m0 * Hd,
                  g_H1l + (long)s * Bm * Hd + (long)m0 * Hd, Hd,
                  g_fcWh + (long)n0 * Hd, g_fcWl + (long)n0 * Hd, Hd,
                  0, 16);
        final_store(acc, out, fc_b, s, m0, n0);
    }
}

extern "C" void kernel_launch(void *const *d_in, const int *in_sizes, int n_in,
                              void *d_out, int out_size) {
    (void)in_sizes; (void)n_in; (void)out_size;
    const float *y0    = (const float *)d_in[0];
    // d_in[1] = t (length only; unused)
    const float *W_ih0 = (const float *)d_in[2];
    const float *W_hh0 = (const float *)d_in[3];
    const float *b_ih0 = (const float *)d_in[4];
    const float *b_hh0 = (const float *)d_in[5];
    const float *W_ih1 = (const float *)d_in[6];
    const float *W_hh1 = (const float *)d_in[7];
    const float *b_ih1 = (const float *)d_in[8];
    const float *b_hh1 = (const float *)d_in[9];
    const float *fc_W  = (const float *)d_in[10];
    const float *fc_b  = (const float *)d_in[11];
    float *out = (float *)d_out;

    cudaFuncSetAttribute(rnn_tc, cudaFuncAttributeMaxDynamicSharedMemorySize, SMEM_BYTES);
    rnn_tc<<<NCTA, NTHR, SMEM_BYTES>>>(y0, W_ih0, W_hh0, b_ih0, b_hh0,
                                       W_ih1, W_hh1, b_ih1, b_hh1,
                                       fc_W, fc_b, out);
}